// round 6
// baseline (speedup 1.0000x reference)
#include <cuda_runtime.h>
#include <cstdint>

#define KSZ 5
#define NBUCKETS 25
#define BATCH 8
#define CHANNELS 96
#define HEIGHT 192
#define WIDTH 192

#define BTX 16            // threads x
#define BTY 16            // threads y
#define NTHREADS (BTX*BTY)
#define PX 4              // output pixels (columns) per thread
#define CH 2              // channels per iteration
#define TILE_OW (BTX*PX)  // 64 output columns per block
#define TILE_OH BTY       // 16 output rows per block
#define HALO 2
#define TROWS (TILE_OH + 2*HALO)   // 20
#define TCOLS (TILE_OW + 2*HALO)   // 68 loaded columns
#define TSTRIDE 72                 // row stride in floats (288B, 16B-aligned)
#define TILE_FLOATS (TROWS * TSTRIDE)

__device__ __forceinline__ void cp_async4(uint32_t smem_dst, const void* gptr, int src_bytes) {
    asm volatile("cp.async.ca.shared.global [%0], [%1], 4, %2;\n"
                 :: "r"(smem_dst), "l"(gptr), "r"(src_bytes));
}
__device__ __forceinline__ void cp_async_commit() {
    asm volatile("cp.async.commit_group;\n" ::: "memory");
}
template <int N>
__device__ __forceinline__ void cp_async_wait() {
    asm volatile("cp.async.wait_group %0;\n" :: "n"(N) : "memory");
}

// Packed dual-FMA on the Blackwell f32x2 datapath (ptxas never emits this from C++).
__device__ __forceinline__ float2 ffma2(float2 a, float2 b, float2 c) {
    unsigned long long au, bu, cu, du;
    au = *reinterpret_cast<unsigned long long*>(&a);
    bu = *reinterpret_cast<unsigned long long*>(&b);
    cu = *reinterpret_cast<unsigned long long*>(&c);
    asm("fma.rn.f32x2 %0, %1, %2, %3;" : "=l"(du) : "l"(au), "l"(bu), "l"(cu));
    return *reinterpret_cast<float2*>(&du);
}

__global__ __launch_bounds__(NTHREADS, 2) void csconv2d_kernel(
    const float* __restrict__ input,        // [B,C,H,W]
    const float* __restrict__ kernel_bank,  // [25,5,5]
    const int* __restrict__ buckets,        // [B,H,W] int32
    float* __restrict__ output)             // [B,C,H,W]
{
    __shared__ __align__(16) float s_tile[2][CH][TILE_FLOATS];  // 2 bufs x 2 ch
    __shared__ __align__(16) float s_bank[640];                 // 625 used

    const int tx = threadIdx.x;
    const int ty = threadIdx.y;
    const int tid = ty * BTX + tx;

    const int w0 = blockIdx.x * TILE_OW;
    const int h0 = blockIdx.y * TILE_OH;
    const int b  = blockIdx.z;

    const int h = h0 + ty;
    const int wbase = w0 + PX * tx;

    for (int i = tid; i < NBUCKETS * KSZ * KSZ; i += NTHREADS)
        s_bank[i] = kernel_bank[i];
    __syncthreads();

    const int4 bk4 = *reinterpret_cast<const int4*>(
        &buckets[((long long)b * HEIGHT + h) * WIDTH + wbase]);
    int bkt[PX] = {bk4.x, bk4.y, bk4.z, bk4.w};
    #pragma unroll
    for (int p = 0; p < PX; p++)
        bkt[p] = min(max(bkt[p], 0), NBUCKETS - 1);

    // Weights packed per pixel-pair: wk01[t] = (w_px0[t], w_px1[t]), wk23 likewise.
    float2 wk01[25], wk23[25];
    #pragma unroll
    for (int t = 0; t < 25; t++) {
        wk01[t] = make_float2(s_bank[bkt[0] * 25 + t], s_bank[bkt[1] * 25 + t]);
        wk23[t] = make_float2(s_bank[bkt[2] * 25 + t], s_bank[bkt[3] * 25 + t]);
    }

    const float* inb  = input  + (size_t)b * CHANNELS * HEIGHT * WIDTH;
    float*       outb = output + (size_t)b * CHANNELS * HEIGHT * WIDTH;

    const uint32_t s_tile_base = (uint32_t)__cvta_generic_to_shared(&s_tile[0][0][0]);

    auto issue_pair = [&](int c0, int buf) {
        #pragma unroll
        for (int cc = 0; cc < CH; cc++) {
            const float* chan = inb + (size_t)(c0 + cc) * HEIGHT * WIDTH;
            #pragma unroll
            for (int idx = tid; idx < TROWS * TCOLS; idx += NTHREADS) {
                const int r   = idx / TCOLS;
                const int col = idx % TCOLS;
                const int gh = h0 + r - HALO;
                const int gw = w0 + col - HALO;
                const bool ok = ((unsigned)gh < HEIGHT) & ((unsigned)gw < WIDTH);
                const float* src = chan + (ok ? ((size_t)gh * WIDTH + gw) : 0);
                const uint32_t dst = s_tile_base
                    + (uint32_t)(((buf * CH + cc) * TILE_FLOATS + r * TSTRIDE + col) * 4);
                cp_async4(dst, src, ok ? 4 : 0);
            }
        }
        cp_async_commit();
    };

    issue_pair(0, 0);

    #pragma unroll 1
    for (int it = 0; it < CHANNELS / CH; it++) {
        const int buf = it & 1;
        const int c0 = it * CH;

        cp_async_wait<0>();
        __syncthreads();

        if (it + 1 < CHANNELS / CH)
            issue_pair(c0 + CH, buf ^ 1);   // overlaps compute below

        float2 acc01[CH], acc23[CH];
        #pragma unroll
        for (int cc = 0; cc < CH; cc++) {
            acc01[cc] = make_float2(0.f, 0.f);
            acc23[cc] = make_float2(0.f, 0.f);
        }

        #pragma unroll
        for (int i = 0; i < KSZ; i++) {
            #pragma unroll
            for (int cc = 0; cc < CH; cc++) {
                const float* row = &s_tile[buf][cc][(ty + i) * TSTRIDE + PX * tx];
                const float4 a  = *reinterpret_cast<const float4*>(row);
                const float4 bq = *reinterpret_cast<const float4*>(row + 4);
                // Sliding pairs P[k] = (v[k], v[k+1]); 4 are free register pairs.
                float2 P[7];
                P[0] = make_float2(a.x, a.y);
                P[1] = make_float2(a.y, a.z);
                P[2] = make_float2(a.z, a.w);
                P[3] = make_float2(a.w, bq.x);
                P[4] = make_float2(bq.x, bq.y);
                P[5] = make_float2(bq.y, bq.z);
                P[6] = make_float2(bq.z, bq.w);
                #pragma unroll
                for (int j = 0; j < KSZ; j++) {
                    acc01[cc] = ffma2(P[j],     wk01[i * KSZ + j], acc01[cc]);
                    acc23[cc] = ffma2(P[j + 2], wk23[i * KSZ + j], acc23[cc]);
                }
            }
        }

        #pragma unroll
        for (int cc = 0; cc < CH; cc++) {
            float4 o = {acc01[cc].x, acc01[cc].y, acc23[cc].x, acc23[cc].y};
            *reinterpret_cast<float4*>(
                &outb[((size_t)(c0 + cc) * HEIGHT + h) * WIDTH + wbase]) = o;
        }
    }
}

extern "C" void kernel_launch(void* const* d_in, const int* in_sizes, int n_in,
                              void* d_out, int out_size)
{
    const float* input       = (const float*)d_in[0];
    const float* kernel_bank = (const float*)d_in[1];
    const int*   buckets     = (const int*)d_in[2];
    float*       output      = (float*)d_out;

    dim3 block(BTX, BTY, 1);
    dim3 grid(WIDTH / TILE_OW, HEIGHT / TILE_OH, BATCH);   // (3, 12, 8)
    csconv2d_kernel<<<grid, block>>>(input, kernel_bank, buckets, output);
}

// round 7
// speedup vs baseline: 1.8698x; 1.8698x over previous
#include <cuda_runtime.h>
#include <cstdint>

#define KSZ 5
#define NBUCKETS 25
#define BATCH 8
#define CHANNELS 96
#define HEIGHT 192
#define WIDTH 192

#define BTX 16            // threads x
#define BTY 16            // threads y
#define NTHREADS (BTX*BTY)
#define PX 4              // output pixels (columns) per thread
#define CH 2              // channels per iteration
#define TILE_OW (BTX*PX)  // 64 output columns per block
#define TILE_OH BTY       // 16 output rows per block
#define HALO 2
#define TROWS (TILE_OH + 2*HALO)   // 20
#define TCOLS (TILE_OW + 2*HALO)   // 68 loaded columns (even)
#define TSTRIDE 72                 // row stride in floats (288B, 16B-aligned)
#define TILE_FLOATS (TROWS * TSTRIDE)
#define NPAIRS (TROWS * (TCOLS/2))  // 20*34 = 680 8-byte pairs per channel tile

__device__ __forceinline__ void cp_async8(uint32_t smem_dst, const void* gptr, int src_bytes) {
    asm volatile("cp.async.ca.shared.global [%0], [%1], 8, %2;\n"
                 :: "r"(smem_dst), "l"(gptr), "r"(src_bytes));
}
__device__ __forceinline__ void cp_async_commit() {
    asm volatile("cp.async.commit_group;\n" ::: "memory");
}
template <int N>
__device__ __forceinline__ void cp_async_wait() {
    asm volatile("cp.async.wait_group %0;\n" :: "n"(N) : "memory");
}

__global__ __launch_bounds__(NTHREADS, 2) void csconv2d_kernel(
    const float* __restrict__ input,        // [B,C,H,W]
    const float* __restrict__ kernel_bank,  // [25,5,5]
    const int* __restrict__ buckets,        // [B,H,W] int32
    float* __restrict__ output)             // [B,C,H,W]
{
    __shared__ __align__(16) float s_tile[2][CH][TILE_FLOATS];  // 2 bufs x 2 ch
    __shared__ __align__(16) float s_bank[640];                 // 625 used

    const int tx = threadIdx.x;
    const int ty = threadIdx.y;
    const int tid = ty * BTX + tx;

    const int w0 = blockIdx.x * TILE_OW;
    const int h0 = blockIdx.y * TILE_OH;
    const int b  = blockIdx.z;

    const int h = h0 + ty;
    const int wbase = w0 + PX * tx;

    for (int i = tid; i < NBUCKETS * KSZ * KSZ; i += NTHREADS)
        s_bank[i] = kernel_bank[i];
    __syncthreads();

    const int4 bk4 = *reinterpret_cast<const int4*>(
        &buckets[((long long)b * HEIGHT + h) * WIDTH + wbase]);
    int bkt[PX] = {bk4.x, bk4.y, bk4.z, bk4.w};
    #pragma unroll
    for (int p = 0; p < PX; p++)
        bkt[p] = min(max(bkt[p], 0), NBUCKETS - 1);

    float wk[PX * 25];
    #pragma unroll
    for (int p = 0; p < PX; p++)
        #pragma unroll
        for (int t = 0; t < 25; t++)
            wk[p * 25 + t] = s_bank[bkt[p] * 25 + t];

    const float* inb  = input  + (size_t)b * CHANNELS * HEIGHT * WIDTH;
    float*       outb = output + (size_t)b * CHANNELS * HEIGHT * WIDTH;

    const uint32_t s_tile_base = (uint32_t)__cvta_generic_to_shared(&s_tile[0][0][0]);

    // Issue async tile loads for channels [c0, c0+CH) into buffer buf (one group).
    // 8-byte cp.async: row origin gw = w0-2 is an even float index, so every
    // 2-float pair is 8B-aligned in global and shared; since w0 % 64 == 0, W-edge
    // pairs are fully in-bounds or fully out (never straddle) -> exact zfill.
    auto issue_pair = [&](int c0, int buf) {
        #pragma unroll
        for (int cc = 0; cc < CH; cc++) {
            const float* chan = inb + (size_t)(c0 + cc) * HEIGHT * WIDTH;
            #pragma unroll
            for (int idx = tid; idx < NPAIRS; idx += NTHREADS) {
                const int r   = idx / (TCOLS / 2);
                const int col = (idx % (TCOLS / 2)) * 2;
                const int gh = h0 + r - HALO;
                const int gw = w0 + col - HALO;
                const bool ok = ((unsigned)gh < HEIGHT) & ((unsigned)gw < WIDTH);
                const float* src = chan + (ok ? ((size_t)gh * WIDTH + gw) : 0);
                const uint32_t dst = s_tile_base
                    + (uint32_t)(((buf * CH + cc) * TILE_FLOATS + r * TSTRIDE + col) * 4);
                cp_async8(dst, src, ok ? 8 : 0);
            }
        }
        cp_async_commit();
    };

    issue_pair(0, 0);

    #pragma unroll 1
    for (int it = 0; it < CHANNELS / CH; it++) {
        const int buf = it & 1;
        const int c0 = it * CH;

        cp_async_wait<0>();   // current pair's data has landed
        __syncthreads();      // visible to all threads; prev buffer fully read

        if (it + 1 < CHANNELS / CH)
            issue_pair(c0 + CH, buf ^ 1);   // overlaps with compute below

        float acc[CH][PX];
        #pragma unroll
        for (int cc = 0; cc < CH; cc++)
            #pragma unroll
            for (int p = 0; p < PX; p++) acc[cc][p] = 0.f;

        #pragma unroll
        for (int i = 0; i < KSZ; i++) {
            #pragma unroll
            for (int cc = 0; cc < CH; cc++) {
                const float* row = &s_tile[buf][cc][(ty + i) * TSTRIDE + PX * tx];
                const float4 a  = *reinterpret_cast<const float4*>(row);
                const float4 bq = *reinterpret_cast<const float4*>(row + 4);
                const float v[8] = {a.x, a.y, a.z, a.w, bq.x, bq.y, bq.z, bq.w};
                #pragma unroll
                for (int p = 0; p < PX; p++)
                    #pragma unroll
                    for (int j = 0; j < KSZ; j++)
                        acc[cc][p] = fmaf(v[p + j], wk[p * 25 + i * KSZ + j], acc[cc][p]);
            }
        }

        #pragma unroll
        for (int cc = 0; cc < CH; cc++) {
            float4 o = {acc[cc][0], acc[cc][1], acc[cc][2], acc[cc][3]};
            *reinterpret_cast<float4*>(
                &outb[((size_t)(c0 + cc) * HEIGHT + h) * WIDTH + wbase]) = o;
        }
    }
}

extern "C" void kernel_launch(void* const* d_in, const int* in_sizes, int n_in,
                              void* d_out, int out_size)
{
    const float* input       = (const float*)d_in[0];
    const float* kernel_bank = (const float*)d_in[1];
    const int*   buckets     = (const int*)d_in[2];
    float*       output      = (float*)d_out;

    dim3 block(BTX, BTY, 1);
    dim3 grid(WIDTH / TILE_OW, HEIGHT / TILE_OH, BATCH);   // (3, 12, 8)
    csconv2d_kernel<<<grid, block>>>(input, kernel_bank, buckets, output);
}

// round 8
// speedup vs baseline: 1.8926x; 1.0122x over previous
#include <cuda_runtime.h>
#include <cstdint>

#define KSZ 5
#define NBUCKETS 25
#define BATCH 8
#define CHANNELS 96
#define HEIGHT 192
#define WIDTH 192

#define BTX 16
#define BTY 16
#define NTHREADS (BTX*BTY)
#define PX 4
#define CH 2
#define NBUF 4
#define TILE_OW (BTX*PX)  // 64
#define TILE_OH BTY       // 16
#define HALO 2
#define TROWS (TILE_OH + 2*HALO)   // 20
#define TCOLS (TILE_OW + 2*HALO)   // 68
#define TSTRIDE 72                 // floats per row (16B-aligned)
#define TILE_FLOATS (TROWS * TSTRIDE)
#define NPAIRS (TROWS * (TCOLS/2))  // 680 8-byte pairs
#define NITER (CHANNELS / CH)       // 48
#define NSLOT 3                     // ceil(680/256)

__device__ __forceinline__ void cp_async8(uint32_t smem_dst, const void* gptr, int src_bytes) {
    asm volatile("cp.async.ca.shared.global [%0], [%1], 8, %2;\n"
                 :: "r"(smem_dst), "l"(gptr), "r"(src_bytes));
}
__device__ __forceinline__ void cp_async_commit() {
    asm volatile("cp.async.commit_group;\n" ::: "memory");
}
template <int N>
__device__ __forceinline__ void cp_async_wait() {
    asm volatile("cp.async.wait_group %0;\n" :: "n"(N) : "memory");
}

__global__ __launch_bounds__(NTHREADS, 2) void csconv2d_kernel(
    const float* __restrict__ input,        // [B,C,H,W]
    const float* __restrict__ kernel_bank,  // [25,5,5]
    const int* __restrict__ buckets,        // [B,H,W] int32
    float* __restrict__ output)             // [B,C,H,W]
{
    __shared__ __align__(16) float s_tile[NBUF][CH][TILE_FLOATS];  // 46 KB
    __shared__ __align__(16) float s_bank[640];

    const int tx = threadIdx.x;
    const int ty = threadIdx.y;
    const int tid = ty * BTX + tx;

    const int w0 = blockIdx.x * TILE_OW;
    const int h0 = blockIdx.y * TILE_OH;
    const int b  = blockIdx.z;

    const int h = h0 + ty;
    const int wbase = w0 + PX * tx;

    for (int i = tid; i < NBUCKETS * KSZ * KSZ; i += NTHREADS)
        s_bank[i] = kernel_bank[i];
    __syncthreads();

    const int4 bk4 = *reinterpret_cast<const int4*>(
        &buckets[((long long)b * HEIGHT + h) * WIDTH + wbase]);
    int bkt[PX] = {bk4.x, bk4.y, bk4.z, bk4.w};
    #pragma unroll
    for (int p = 0; p < PX; p++)
        bkt[p] = min(max(bkt[p], 0), NBUCKETS - 1);

    float wk[PX * 25];
    #pragma unroll
    for (int p = 0; p < PX; p++)
        #pragma unroll
        for (int t = 0; t < 25; t++)
            wk[p * 25 + t] = s_bank[bkt[p] * 25 + t];

    const float* inb  = input  + (size_t)b * CHANNELS * HEIGHT * WIDTH;
    float*       outb = output + (size_t)b * CHANNELS * HEIGHT * WIDTH;

    const uint32_t s_tile_base = (uint32_t)__cvta_generic_to_shared(&s_tile[0][0][0]);

    // Precompute this thread's fill slots (iteration-invariant): smem offset
    // (relative to a channel-tile base, bytes), gmem offset (relative to a
    // channel base, floats), byte count (8 or 0 for zfill).
    int   g_rel[NSLOT];
    uint32_t s_rel[NSLOT];
    int   nbytes[NSLOT];
    #pragma unroll
    for (int s = 0; s < NSLOT; s++) {
        const int idx = tid + s * NTHREADS;
        if (idx < NPAIRS) {
            const int r   = idx / (TCOLS / 2);
            const int col = (idx % (TCOLS / 2)) * 2;
            const int gh = h0 + r - HALO;
            const int gw = w0 + col - HALO;
            const bool ok = ((unsigned)gh < HEIGHT) & ((unsigned)gw < WIDTH);
            g_rel[s]  = ok ? (gh * WIDTH + gw) : 0;
            s_rel[s]  = (uint32_t)((r * TSTRIDE + col) * 4);
            nbytes[s] = ok ? 8 : 0;
        } else {
            g_rel[s] = 0; s_rel[s] = 0; nbytes[s] = -1;  // inactive
        }
    }

    auto issue_pair = [&](int c0, int buf) {
        #pragma unroll
        for (int cc = 0; cc < CH; cc++) {
            const float* chan = inb + (size_t)(c0 + cc) * (HEIGHT * WIDTH);
            const uint32_t sbase = s_tile_base
                + (uint32_t)((buf * CH + cc) * TILE_FLOATS * 4);
            #pragma unroll
            for (int s = 0; s < NSLOT; s++)
                if (nbytes[s] >= 0)
                    cp_async8(sbase + s_rel[s], chan + g_rel[s], nbytes[s]);
        }
        cp_async_commit();
    };

    // Prologue: 3 groups in flight.
    issue_pair(0, 0);
    issue_pair(CH, 1);
    issue_pair(2 * CH, 2);

    #pragma unroll 1
    for (int it = 0; it < NITER; it++) {
        const int buf = it & (NBUF - 1);
        const int c0 = it * CH;

        // Ensure group `it` has landed. Outstanding groups after it: min(2, 47-it).
        const int rem = (NITER - 1) - it;
        if (rem >= 2)      cp_async_wait<2>();
        else if (rem == 1) cp_async_wait<1>();
        else               cp_async_wait<0>();
        __syncthreads();   // data visible to all; buf (it+3)&3 fully read (it-1)

        if (it + 3 < NITER)
            issue_pair(c0 + 3 * CH, (it + 3) & (NBUF - 1));

        float acc[CH][PX];
        #pragma unroll
        for (int cc = 0; cc < CH; cc++)
            #pragma unroll
            for (int p = 0; p < PX; p++) acc[cc][p] = 0.f;

        #pragma unroll
        for (int i = 0; i < KSZ; i++) {
            #pragma unroll
            for (int cc = 0; cc < CH; cc++) {
                const float* row = &s_tile[buf][cc][(ty + i) * TSTRIDE + PX * tx];
                const float4 a  = *reinterpret_cast<const float4*>(row);
                const float4 bq = *reinterpret_cast<const float4*>(row + 4);
                const float v[8] = {a.x, a.y, a.z, a.w, bq.x, bq.y, bq.z, bq.w};
                #pragma unroll
                for (int p = 0; p < PX; p++)
                    #pragma unroll
                    for (int j = 0; j < KSZ; j++)
                        acc[cc][p] = fmaf(v[p + j], wk[p * 25 + i * KSZ + j], acc[cc][p]);
            }
        }

        #pragma unroll
        for (int cc = 0; cc < CH; cc++) {
            float4 o = {acc[cc][0], acc[cc][1], acc[cc][2], acc[cc][3]};
            *reinterpret_cast<float4*>(
                &outb[((size_t)(c0 + cc) * HEIGHT + h) * WIDTH + wbase]) = o;
        }
    }
}

extern "C" void kernel_launch(void* const* d_in, const int* in_sizes, int n_in,
                              void* d_out, int out_size)
{
    const float* input       = (const float*)d_in[0];
    const float* kernel_bank = (const float*)d_in[1];
    const int*   buckets     = (const int*)d_in[2];
    float*       output      = (float*)d_out;

    dim3 block(BTX, BTY, 1);
    dim3 grid(WIDTH / TILE_OW, HEIGHT / TILE_OH, BATCH);   // (3, 12, 8)
    csconv2d_kernel<<<grid, block>>>(input, kernel_bank, buckets, output);
}